// round 14
// baseline (speedup 1.0000x reference)
#include <cuda_runtime.h>
#include <math.h>
#include <stdint.h>

#define NROWS   262144
#define TILE_R  16                      // rows per pipeline stage (8 KB)
#define STAGES  4
#define NTILES  (NROWS / TILE_R)        // 16384
#define NCTA    2220                    // 3.0 exact waves at 5 CTAs/SM x 148
#define T8      844                     // CTAs doing 8 tiles (rest do 7)

__device__ __forceinline__ void cpa16(uint32_t dst, const float4* src) {
    asm volatile("cp.async.cg.shared.global [%0], [%1], 16;"
                 :: "r"(dst), "l"(src));
}
__device__ __forceinline__ void cpa_commit() {
    asm volatile("cp.async.commit_group;");
}
__device__ __forceinline__ void cpa_wait3() {
    asm volatile("cp.async.wait_group 3;");
}

__global__ void __launch_bounds__(128)
bdla_main(const float4* __restrict__ x, float4* __restrict__ y,
          const float* __restrict__ Wd, const float* __restrict__ s,
          const float* __restrict__ U, const float* __restrict__ V) {
    __shared__ float4 sx[STAGES][TILE_R * 32];   // 4 x 8 KB

    const int tid  = threadIdx.x;
    const int lane = tid & 31;
    const int wid  = tid >> 5;                   // 0..3
    const int j    = lane >> 2;                  // block id
    const int q    = lane & 3;                   // output quad

    // Uneven static tiling: CTAs [0,T8) take 8 tiles, the rest 7.
    const int cta  = blockIdx.x;
    const int nt   = (cta < T8) ? 8 : 7;
    const int til0 = (cta < T8) ? cta * 8 : T8 * 8 + (cta - T8) * 7;

    const float4* gsrc0 = x + (size_t)til0 * TILE_R * 32;
    const uint32_t sbase = (uint32_t)__cvta_generic_to_shared(&sx[0][0]);

    // Prologue: start DRAM traffic for tiles 0..2 first (nt >= 7 > 3).
    #pragma unroll
    for (int t = 0; t < STAGES - 1; ++t) {
        const uint32_t dst0 = sbase + (uint32_t)(t * TILE_R * 512);
        const float4* src0 = gsrc0 + t * TILE_R * 32;
        #pragma unroll
        for (int i = 0; i < 4; ++i)
            cpa16(dst0 + (tid + 128 * i) * 16u, src0 + tid + 128 * i);
        cpa_commit();
    }

    // Direct per-lane weight build, TRANSPOSED layout (no smem, no sync):
    //   wt[o*4+dq].c = M[j][4*dq+c][4*q+o]   (weight for input d=4dq+c,
    //                                          output ob=4q+o of block j)
    float4 wt[16];
    if (j == 1 || j == 4 || j == 7) {
        // Diagonal: row ob=4q+o has single nonzero at d=ob -> dq==q, comp o.
        const int k = (j - 1) / 3;
        const float4 sv = *(const float4*)&s[k * 16 + 4 * q];
        #pragma unroll
        for (int i = 0; i < 16; ++i) wt[i] = make_float4(0.f, 0.f, 0.f, 0.f);
        wt[0 * 4 + q].x = sv.x;
        wt[1 * 4 + q].y = sv.y;
        wt[2 * 4 + q].z = sv.z;
        wt[3 * 4 + q].w = sv.w;
    } else if (j == 2 || j == 5) {
        // Lowrank: wt[o][d] = dot(U[ob], V[d]).
        const int k = (j - 2) / 3;
        float4 u4[4];
        #pragma unroll
        for (int o = 0; o < 4; ++o)
            u4[o] = *(const float4*)&U[k * 64 + (4 * q + o) * 4];
        #pragma unroll
        for (int dd = 0; dd < 16; ++dd) {
            const float4 vd = *(const float4*)&V[k * 64 + dd * 4];
            #pragma unroll
            for (int o = 0; o < 4; ++o) {
                float val = u4[o].x * vd.x;
                val = fmaf(u4[o].y, vd.y, val);
                val = fmaf(u4[o].z, vd.z, val);
                val = fmaf(u4[o].w, vd.w, val);
                float* wp = (float*)&wt[o * 4 + (dd >> 2)];
                wp[dd & 3] = val;
            }
        }
    } else {
        // Dense: wt[o][*] = row (4q+o) of W[k] -> 16 coalesced LDG.128.
        const int k = j / 3;
        #pragma unroll
        for (int o = 0; o < 4; ++o) {
            const float4* rw = (const float4*)&Wd[k * 256 + (4 * q + o) * 16];
            #pragma unroll
            for (int dq = 0; dq < 4; ++dq) wt[o * 4 + dq] = rw[dq];
        }
    }

    int stage = 0, pstage = STAGES - 1;
    #pragma unroll 1
    for (int t = 0; t < nt; ++t) {
        // Issue tile t+STAGES-1; empty commit groups keep wait_group aligned.
        const int tp = t + STAGES - 1;
        if (tp < nt) {
            const uint32_t dst0 = sbase + (uint32_t)(pstage * TILE_R * 512);
            const float4* src0 = gsrc0 + tp * TILE_R * 32;
            #pragma unroll
            for (int i = 0; i < 4; ++i)
                cpa16(dst0 + (tid + 128 * i) * 16u, src0 + tid + 128 * i);
        }
        cpa_commit();

        cpa_wait3();              // tile t's group complete (<=3 pending)
        __syncthreads();          // visible to all warps

        const float4* tile = &sx[stage][0];

        // Each warp computes 4 rows of the 16-row tile.
        #pragma unroll
        for (int k = 0; k < 4; ++k) {
            const int rit = wid + 4 * k;
            const float4* rowp = tile + rit * 32 + j * 4;

            float y0 = 0.f, y1 = 0.f, y2 = 0.f, y3 = 0.f;
            #pragma unroll
            for (int sb = 0; sb < 4; ++sb) {
                const float4 a = rowp[sb];           // quad-broadcast LDS.128
                const float4 w0 = wt[0 * 4 + sb];
                const float4 w1 = wt[1 * 4 + sb];
                const float4 w2 = wt[2 * 4 + sb];
                const float4 w3 = wt[3 * 4 + sb];
                y0 = fmaf(a.x, w0.x, y0); y0 = fmaf(a.y, w0.y, y0);
                y0 = fmaf(a.z, w0.z, y0); y0 = fmaf(a.w, w0.w, y0);
                y1 = fmaf(a.x, w1.x, y1); y1 = fmaf(a.y, w1.y, y1);
                y1 = fmaf(a.z, w1.z, y1); y1 = fmaf(a.w, w1.w, y1);
                y2 = fmaf(a.x, w2.x, y2); y2 = fmaf(a.y, w2.y, y2);
                y2 = fmaf(a.z, w2.z, y2); y2 = fmaf(a.w, w2.w, y2);
                y3 = fmaf(a.x, w3.x, y3); y3 = fmaf(a.y, w3.y, y3);
                y3 = fmaf(a.z, w3.z, y3); y3 = fmaf(a.w, w3.w, y3);
            }

            // Row L2 norm across all 32 lanes.
            float ss = y0 * y0;
            ss = fmaf(y1, y1, ss); ss = fmaf(y2, y2, ss); ss = fmaf(y3, y3, ss);
            #pragma unroll
            for (int m = 16; m >= 1; m >>= 1)
                ss += __shfl_xor_sync(0xffffffffu, ss, m);
            const float inv = rsqrtf(ss);

            const unsigned grow = (unsigned)(til0 + t) * TILE_R + rit;
            y[(size_t)grow * 32 + lane] =
                make_float4(y0 * inv, y1 * inv, y2 * inv, y3 * inv);
        }

        __syncthreads();          // stage reused by the issue at t+1

        stage  = (stage  == STAGES - 1) ? 0 : stage + 1;
        pstage = (pstage == STAGES - 1) ? 0 : pstage + 1;
    }
}

extern "C" void kernel_launch(void* const* d_in, const int* in_sizes, int n_in,
                              void* d_out, int out_size) {
    const float* x = (const float*)d_in[0];
    const float* W = (const float*)d_in[1];
    const float* s = (const float*)d_in[2];
    const float* U = (const float*)d_in[3];
    const float* V = (const float*)d_in[4];
    float* out = (float*)d_out;

    bdla_main<<<NCTA, 128>>>((const float4*)x, (float4*)out, W, s, U, V);
}

// round 15
// speedup vs baseline: 1.7371x; 1.7371x over previous
#include <cuda_runtime.h>
#include <math.h>
#include <stdint.h>

#define NROWS   262144
#define TILE_R  16                      // rows per pipeline stage (8 KB)
#define STAGES  4
#define NTILES  (NROWS / TILE_R)        // 16384
#define NCTA    2220                    // 3.0 exact waves at 5 CTAs/SM x 148
#define T8      844                     // CTAs doing 8 tiles (rest do 7)

__device__ __forceinline__ void cpa16(uint32_t dst, const float4* src) {
    asm volatile("cp.async.cg.shared.global [%0], [%1], 16;"
                 :: "r"(dst), "l"(src));
}
__device__ __forceinline__ void cpa_commit() {
    asm volatile("cp.async.commit_group;");
}
__device__ __forceinline__ void cpa_wait3() {
    asm volatile("cp.async.wait_group 3;");
}

__global__ void __launch_bounds__(128, 5)
bdla_main(const float4* __restrict__ x, float4* __restrict__ y,
          const float* __restrict__ Wd, const float* __restrict__ s,
          const float* __restrict__ U, const float* __restrict__ V) {
    __shared__ float4 sx[STAGES][TILE_R * 32];   // 4 x 8 KB
    __shared__ float  swt[2048];                 // swt[j*256 + d*16 + ob]

    const int tid  = threadIdx.x;
    const int lane = tid & 31;
    const int wid  = tid >> 5;                   // 0..3
    const int j    = lane >> 2;                  // block id
    const int q    = lane & 3;                   // output quad

    // Uneven static tiling: CTAs [0,T8) take 8 tiles, the rest 7.
    const int cta  = blockIdx.x;
    const int nt   = (cta < T8) ? 8 : 7;
    const int til0 = (cta < T8) ? cta * 8 : T8 * 8 + (cta - T8) * 7;

    const float4* gsrc0 = x + (size_t)til0 * TILE_R * 32;
    const uint32_t sbase = (uint32_t)__cvta_generic_to_shared(&sx[0][0]);

    // Prologue: start DRAM traffic for tiles 0..2 first (nt >= 7 > 3).
    #pragma unroll
    for (int t = 0; t < STAGES - 1; ++t) {
        const uint32_t dst0 = sbase + (uint32_t)(t * TILE_R * 512);
        const float4* src0 = gsrc0 + t * TILE_R * 32;
        #pragma unroll
        for (int i = 0; i < 4; ++i)
            cpa16(dst0 + (tid + 128 * i) * 16u, src0 + tid + 128 * i);
        cpa_commit();
    }

    // Build unified per-block 16x16 matrices in smem, fully unrolled so all
    // parameter LDGs overlap (R13-proven, regs=96).
    #pragma unroll
    for (int i = 0; i < 16; ++i) {
        const int e = tid + 128 * i;
        const int jj = e >> 8;
        const int rem = e & 255;
        const int d = rem >> 4;
        const int o = rem & 15;
        float val;
        if (jj == 0 || jj == 3 || jj == 6) {
            const int k = jj / 3;
            val = Wd[k * 256 + o * 16 + d];
        } else if (jj == 1 || jj == 4 || jj == 7) {
            const int k = (jj - 1) / 3;
            val = (d == o) ? s[k * 16 + d] : 0.0f;
        } else {
            const int k = (jj - 2) / 3;
            float acc = 0.0f;
            #pragma unroll
            for (int r = 0; r < 4; ++r)
                acc += V[k * 64 + d * 4 + r] * U[k * 64 + o * 4 + r];
            val = acc;
        }
        swt[e] = val;
    }
    __syncthreads();

    // 64 weight registers per lane: w[d] = M[j][d][4q..4q+3].
    float4 w[16];
    {
        const float4* Mp = (const float4*)&swt[j * 256 + q * 4];
        #pragma unroll
        for (int d = 0; d < 16; ++d) w[d] = Mp[d * 4];
    }
    // swt read-only from here on.

    int stage = 0, pstage = STAGES - 1;
    #pragma unroll 1
    for (int t = 0; t < nt; ++t) {
        // Issue tile t+STAGES-1; empty commit groups keep wait_group aligned.
        const int tp = t + STAGES - 1;
        if (tp < nt) {
            const uint32_t dst0 = sbase + (uint32_t)(pstage * TILE_R * 512);
            const float4* src0 = gsrc0 + tp * TILE_R * 32;
            #pragma unroll
            for (int i = 0; i < 4; ++i)
                cpa16(dst0 + (tid + 128 * i) * 16u, src0 + tid + 128 * i);
        }
        cpa_commit();

        cpa_wait3();              // tile t's group complete (<=3 pending)
        __syncthreads();          // visible to all warps

        const float4* tile = &sx[stage][0];

        // Each warp computes 4 rows of the 16-row tile.
        #pragma unroll
        for (int k = 0; k < 4; ++k) {
            const int rit = wid + 4 * k;
            const float4* rowp = tile + rit * 32 + j * 4;

            float y0 = 0.f, y1 = 0.f, y2 = 0.f, y3 = 0.f;
            #pragma unroll
            for (int sb = 0; sb < 4; ++sb) {
                const float4 a = rowp[sb];           // quad-broadcast LDS.128
                const float4 w0 = w[4 * sb + 0];
                const float4 w1 = w[4 * sb + 1];
                const float4 w2 = w[4 * sb + 2];
                const float4 w3 = w[4 * sb + 3];
                y0 = fmaf(a.x, w0.x, y0); y1 = fmaf(a.x, w0.y, y1);
                y2 = fmaf(a.x, w0.z, y2); y3 = fmaf(a.x, w0.w, y3);
                y0 = fmaf(a.y, w1.x, y0); y1 = fmaf(a.y, w1.y, y1);
                y2 = fmaf(a.y, w1.z, y2); y3 = fmaf(a.y, w1.w, y3);
                y0 = fmaf(a.z, w2.x, y0); y1 = fmaf(a.z, w2.y, y1);
                y2 = fmaf(a.z, w2.z, y2); y3 = fmaf(a.z, w2.w, y3);
                y0 = fmaf(a.w, w3.x, y0); y1 = fmaf(a.w, w3.y, y1);
                y2 = fmaf(a.w, w3.z, y2); y3 = fmaf(a.w, w3.w, y3);
            }

            // Row L2 norm across all 32 lanes.
            float ss = y0 * y0;
            ss = fmaf(y1, y1, ss); ss = fmaf(y2, y2, ss); ss = fmaf(y3, y3, ss);
            #pragma unroll
            for (int m = 16; m >= 1; m >>= 1)
                ss += __shfl_xor_sync(0xffffffffu, ss, m);
            const float inv = rsqrtf(ss);

            const unsigned grow = (unsigned)(til0 + t) * TILE_R + rit;
            y[(size_t)grow * 32 + lane] =
                make_float4(y0 * inv, y1 * inv, y2 * inv, y3 * inv);
        }

        __syncthreads();          // stage reused by the issue at t+1

        stage  = (stage  == STAGES - 1) ? 0 : stage + 1;
        pstage = (pstage == STAGES - 1) ? 0 : pstage + 1;
    }
}

extern "C" void kernel_launch(void* const* d_in, const int* in_sizes, int n_in,
                              void* d_out, int out_size) {
    const float* x = (const float*)d_in[0];
    const float* W = (const float*)d_in[1];
    const float* s = (const float*)d_in[2];
    const float* U = (const float*)d_in[3];
    const float* V = (const float*)d_in[4];
    float* out = (float*)d_out;

    bdla_main<<<NCTA, 128>>>((const float4*)x, (float4*)out, W, s, U, V);
}